// round 3
// baseline (speedup 1.0000x reference)
#include <cuda_runtime.h>
#include <cuda_bf16.h>

// Problem constants
#define TOTAL_N 262144      // B*N nodes
#define NEDGE   4194304
#define NEDGE4  1048576     // NEDGE/4
#define NPTS    32768       // N
#define NBATCH  8
#define CBOUT   128
#define NSTATS  90          // 12 sums + 78 upper-triangle second moments

// ---------------------------------------------------------------------------
// Device scratch (static allocations only — no cudaMalloc allowed)
// ---------------------------------------------------------------------------
__device__ float  g_deg[TOTAL_N];
__device__ float  g_dis[TOTAL_N];
__device__ float4 g_t0[TOTAL_N];
__device__ float4 g_t1[TOTAL_N];
__device__ float4 g_t2[TOTAL_N];
__device__ float4 g_t3[TOTAL_N];
__device__ float  g_nw[NEDGE];
__device__ double g_stats[NSTATS];
__device__ float  g_wfT[CBOUT * 12];   // folded weights, [c][a] layout (48B rows, 16B aligned)
__device__ float  g_sh[CBOUT];         // folded shift per channel

// ---------------------------------------------------------------------------
// 1) init: zero degree, T1 accumulator, stats
// ---------------------------------------------------------------------------
__global__ void k_init() {
    int i = blockIdx.x * blockDim.x + threadIdx.x;   // TOTAL_N threads exactly
    g_deg[i] = 0.f;
    g_t1[i]  = make_float4(0.f, 0.f, 0.f, 0.f);
    if (i < NSTATS) g_stats[i] = 0.0;
}

// ---------------------------------------------------------------------------
// 2) degree: deg[src] += w  (self-loops removed)
// ---------------------------------------------------------------------------
__global__ __launch_bounds__(256) void k_deg(const int* __restrict__ src,
                                             const int* __restrict__ dst,
                                             const float* __restrict__ ew) {
    int i = blockIdx.x * blockDim.x + threadIdx.x;   // NEDGE4 threads
    int4   s = ((const int4*)src)[i];
    int4   d = ((const int4*)dst)[i];
    float4 w = ((const float4*)ew)[i];
    if (s.x != d.x) atomicAdd(&g_deg[s.x], w.x);
    if (s.y != d.y) atomicAdd(&g_deg[s.y], w.y);
    if (s.z != d.z) atomicAdd(&g_deg[s.z], w.z);
    if (s.w != d.w) atomicAdd(&g_deg[s.w], w.w);
}

// ---------------------------------------------------------------------------
// 3) per-node: dis = deg>0 ? rsqrt(max(deg,1e-12)) : 0 ;  T0 = x ;  T2 = -T0
// ---------------------------------------------------------------------------
__global__ void k_node(const float* __restrict__ x) {
    int i = blockIdx.x * blockDim.x + threadIdx.x;   // TOTAL_N threads
    float dg = g_deg[i];
    g_dis[i] = (dg > 0.f) ? rsqrtf(fmaxf(dg, 1e-12f)) : 0.f;
    int b = i >> 15;          // / NPTS
    int n = i & (NPTS - 1);
    const float* xb = x + (size_t)b * 3 * NPTS + n;
    float v0 = xb[0];
    float v1 = xb[NPTS];
    float v2 = xb[2 * NPTS];
    g_t0[i] = make_float4( v0,  v1,  v2, 0.f);
    g_t2[i] = make_float4(-v0, -v1, -v2, 0.f);
}

// ---------------------------------------------------------------------------
// 4) normalized edge weights: nw = -dis[src] * w * dis[dst]  (0 on self loop)
// ---------------------------------------------------------------------------
__global__ __launch_bounds__(256) void k_normw(const int* __restrict__ src,
                                               const int* __restrict__ dst,
                                               const float* __restrict__ ew) {
    int i = blockIdx.x * blockDim.x + threadIdx.x;   // NEDGE4 threads
    int4   s = ((const int4*)src)[i];
    int4   d = ((const int4*)dst)[i];
    float4 w = ((const float4*)ew)[i];
    float4 o;
    o.x = (s.x == d.x) ? 0.f : -g_dis[s.x] * w.x * g_dis[d.x];
    o.y = (s.y == d.y) ? 0.f : -g_dis[s.y] * w.y * g_dis[d.y];
    o.z = (s.z == d.z) ? 0.f : -g_dis[s.z] * w.z * g_dis[d.z];
    o.w = (s.w == d.w) ? 0.f : -g_dis[s.w] * w.w * g_dis[d.w];
    ((float4*)g_nw)[i] = o;
}

// ---------------------------------------------------------------------------
// 5) propagation (scatter-add):  tout[dst] += scale * nw * tin[src]
//    PASS 1: t0 -> t1 (scale 1);  PASS 2: t1 -> t2 (scale 2);  PASS 3: t2 -> t3 (scale 2)
// ---------------------------------------------------------------------------
__device__ __forceinline__ void edge_add(const float4* __restrict__ tin,
                                         float4* __restrict__ tout,
                                         int s, int d, float w) {
    if (w != 0.f) {
        float4 t = tin[s];
        atomicAdd(&tout[d].x, w * t.x);
        atomicAdd(&tout[d].y, w * t.y);
        atomicAdd(&tout[d].z, w * t.z);
    }
}

template <int PASS>
__global__ __launch_bounds__(256) void k_prop(const int* __restrict__ src,
                                              const int* __restrict__ dst) {
    int i = blockIdx.x * blockDim.x + threadIdx.x;   // NEDGE4 threads
    int4   s = ((const int4*)src)[i];
    int4   d = ((const int4*)dst)[i];
    float4 w = ((const float4*)g_nw)[i];
    const float4* tin  = (PASS == 1) ? g_t0 : (PASS == 2) ? g_t1 : g_t2;
    float4*       tout = (PASS == 1) ? g_t1 : (PASS == 2) ? g_t2 : g_t3;
    const float sc = (PASS == 1) ? 1.f : 2.f;
    edge_add(tin, tout, s.x, d.x, sc * w.x);
    edge_add(tin, tout, s.y, d.y, sc * w.y);
    edge_add(tin, tout, s.z, d.z, sc * w.z);
    edge_add(tin, tout, s.w, d.w, sc * w.w);
}

// T3 initialization = -T1 (after prop1, before prop3 accumulates into it)
__global__ void k_negt1() {
    int i = blockIdx.x * blockDim.x + threadIdx.x;   // TOTAL_N threads
    float4 v = g_t1[i];
    g_t3[i] = make_float4(-v.x, -v.y, -v.z, 0.f);
}

// ---------------------------------------------------------------------------
// 6) stats: Σ v  (12)  and  Σ v vᵀ upper triangle (78), over all nodes.
//    v = concat(T0.xyz, T1.xyz, T2.xyz, T3.xyz)
// ---------------------------------------------------------------------------
__global__ __launch_bounds__(128) void k_stats() {
    int t = blockIdx.x * 128 + threadIdx.x;          // 32768 threads, 8 nodes each
    float acc[NSTATS];
#pragma unroll
    for (int k = 0; k < NSTATS; k++) acc[k] = 0.f;

    for (int it = 0; it < 8; it++) {
        int i = t + it * 32768;
        float v[12];
        float4 a = g_t0[i]; v[0] = a.x; v[1] = a.y; v[2]  = a.z;
        float4 b = g_t1[i]; v[3] = b.x; v[4] = b.y; v[5]  = b.z;
        float4 c = g_t2[i]; v[6] = c.x; v[7] = c.y; v[8]  = c.z;
        float4 d = g_t3[i]; v[9] = d.x; v[10] = d.y; v[11] = d.z;
        int idx = 12;
#pragma unroll
        for (int p = 0; p < 12; p++) {
            acc[p] += v[p];
#pragma unroll
            for (int q = p; q < 12; q++) acc[idx++] += v[p] * v[q];
        }
    }
    // warp reduce then one double-atomic per warp per stat
    int lane = threadIdx.x & 31;
#pragma unroll
    for (int k = 0; k < NSTATS; k++) {
        float x = acc[k];
        x += __shfl_down_sync(0xffffffffu, x, 16);
        x += __shfl_down_sync(0xffffffffu, x, 8);
        x += __shfl_down_sync(0xffffffffu, x, 4);
        x += __shfl_down_sync(0xffffffffu, x, 2);
        x += __shfl_down_sync(0xffffffffu, x, 1);
        if (lane == 0) atomicAdd(&g_stats[k], (double)x);
    }
}

// ---------------------------------------------------------------------------
// 7) BN params: exact batch mean/var per channel from (Σv, Σvvᵀ), fold into
//    per-channel scale/shift and pre-scaled weights.
//    out_c = v·w_c + bias_c ;  mean = m + bias_c with m = (Σv·w_c)/Ntot ;
//    var  = w_cᵀ M w_c /Ntot − m²   (bias cancels in var)
//    Final value: (v·w + bias − mean)·scale + beta = (v·w − m)·scale + beta
//    => shift = beta − m·scale   (bias cancels)
// ---------------------------------------------------------------------------
__global__ void k_bnparam(const float* __restrict__ weight,  // (12, 128) flattened (K*C_IN, C_OUT)
                          const float* __restrict__ bias,
                          const float* __restrict__ gamma,
                          const float* __restrict__ beta) {
    __shared__ double S[NSTATS];
    int c = threadIdx.x;                              // 128 threads
    if (c < NSTATS) S[c] = g_stats[c];
    __syncthreads();

    double wv[12];
#pragma unroll
    for (int a = 0; a < 12; a++) wv[a] = (double)weight[a * CBOUT + c];

    const double invN = 1.0 / (double)TOTAL_N;
    double m = 0.0;
#pragma unroll
    for (int a = 0; a < 12; a++) m += S[a] * wv[a];
    m *= invN;

    double q = 0.0;
    int idx = 12;
#pragma unroll
    for (int a = 0; a < 12; a++) {
#pragma unroll
        for (int b = a; b < 12; b++) {
            double term = S[idx++] * wv[a] * wv[b];
            q += (a == b) ? term : 2.0 * term;
        }
    }
    q *= invN;

    double var = q - m * m;
    if (var < 0.0) var = 0.0;
    (void)bias;  // bias cancels between pre-BN value and batch mean
    double scale = (double)gamma[c] * rsqrt(var + 1e-5);
    g_sh[c] = (float)((double)beta[c] - m * scale);
#pragma unroll
    for (int a = 0; a < 12; a++)
        g_wfT[c * 12 + a] = (float)(wv[a] * scale);
}

// ---------------------------------------------------------------------------
// 8) final fused GEMV + BN + ReLU, writing directly in (B, C_OUT, N) layout.
//    128-node tiles; lanes map to consecutive n => fully coalesced 128B stores.
// ---------------------------------------------------------------------------
__global__ __launch_bounds__(256) void k_final(float* __restrict__ out) {
    __shared__ __align__(16) float swf[CBOUT * 12];  // [c][a], float4-readable rows
    __shared__ float ssh[CBOUT];

    int tid = threadIdx.x;
    for (int k = tid; k < CBOUT * 12; k += 256) swf[k] = g_wfT[k];
    if (tid < CBOUT) ssh[tid] = g_sh[tid];
    __syncthreads();

    int w    = tid >> 5;
    int lane = tid & 31;
    int j    = (w & 3) * 32 + lane;        // node within the 128-node tile
    int cg   = w >> 2;                     // channel half: 0 or 1
    int i    = blockIdx.x * 128 + j;       // global node (tile never straddles a batch)

    float4 a = g_t0[i], b = g_t1[i], c = g_t2[i], d = g_t3[i];
    float v[12] = { a.x, a.y, a.z,  b.x, b.y, b.z,
                    c.x, c.y, c.z,  d.x, d.y, d.z };

    int bb = i >> 15;
    int n  = i & (NPTS - 1);
    float* obase = out + ((size_t)bb * CBOUT) * NPTS + n;

#pragma unroll 8
    for (int k = 0; k < 64; k++) {
        int ch = cg * 64 + k;
        const float4* wr = (const float4*)(swf + ch * 12);
        float4 w0 = wr[0], w1 = wr[1], w2 = wr[2];
        float r = ssh[ch];
        r += v[0] * w0.x + v[1]  * w0.y + v[2]  * w0.z + v[3] * w0.w;
        r += v[4] * w1.x + v[5]  * w1.y + v[6]  * w1.z + v[7] * w1.w;
        r += v[8] * w2.x + v[9]  * w2.y + v[10] * w2.z + v[11] * w2.w;
        obase[(size_t)ch * NPTS] = fmaxf(r, 0.f);
    }
}

// ---------------------------------------------------------------------------
// launch
// ---------------------------------------------------------------------------
extern "C" void kernel_launch(void* const* d_in, const int* in_sizes, int n_in,
                              void* d_out, int out_size) {
    const float* x      = (const float*)d_in[0];
    const int*   eidx   = (const int*)d_in[1];
    const float* ew     = (const float*)d_in[2];
    const float* weight = (const float*)d_in[3];
    const float* bias   = (const float*)d_in[4];
    const float* gamma  = (const float*)d_in[5];
    const float* beta   = (const float*)d_in[6];
    float* out = (float*)d_out;

    const int* src = eidx;          // edge_index[0]
    const int* dst = eidx + NEDGE;  // edge_index[1]

    dim3 bN(256);
    dim3 gN(TOTAL_N / 256);         // 1024 blocks, node-sized kernels
    dim3 gE(NEDGE4 / 256);          // 4096 blocks, edge-sized kernels

    k_init  <<<gN, bN>>>();
    k_deg   <<<gE, bN>>>(src, dst, ew);
    k_node  <<<gN, bN>>>(x);
    k_normw <<<gE, bN>>>(src, dst, ew);
    k_prop<1><<<gE, bN>>>(src, dst);   // t1  = L t0
    k_negt1 <<<gN, bN>>>();            // t3  = -t1
    k_prop<2><<<gE, bN>>>(src, dst);   // t2 += 2 L t1   (t2 pre-init to -t0)
    k_prop<3><<<gE, bN>>>(src, dst);   // t3 += 2 L t2
    k_stats <<<256, 128>>>();
    k_bnparam<<<1, 128>>>(weight, bias, gamma, beta);
    k_final <<<TOTAL_N / 128, 256>>>(out);
}

// round 4
// speedup vs baseline: 1.4440x; 1.4440x over previous
#include <cuda_runtime.h>
#include <cuda_bf16.h>

// Problem constants
#define TOTAL_N 262144      // B*N nodes
#define NEDGE   4194304
#define NEDGE4  1048576     // NEDGE/4
#define NPTS    32768       // N
#define NBATCH  8
#define CBOUT   128
#define NSTATS  90          // 12 sums + 78 upper-triangle second moments

// ---------------------------------------------------------------------------
// Device scratch (static allocations only — no cudaMalloc allowed)
// ---------------------------------------------------------------------------
__device__ float  g_deg[TOTAL_N];
__device__ float  g_dis[TOTAL_N];
__device__ float4 g_t0[TOTAL_N];
__device__ float4 g_t1[TOTAL_N];
__device__ float4 g_t2[TOTAL_N];
__device__ float4 g_t3[TOTAL_N];
__device__ float  g_nw[NEDGE];
__device__ double g_stats[NSTATS];
__device__ float  g_wfT[CBOUT * 12];   // folded weights, [c][a] layout
__device__ float  g_sh[CBOUT];         // folded shift per channel

// one vector reduction per edge: tout[d] += {wx, wy, wz, 0}
__device__ __forceinline__ void red_v4(float4* addr, float x, float y, float z) {
    asm volatile("red.global.add.v4.f32 [%0], {%1, %2, %3, %4};"
                 :: "l"(addr), "f"(x), "f"(y), "f"(z), "f"(0.f) : "memory");
}

// ---------------------------------------------------------------------------
// 1) init: zero degree, T1 accumulator, stats
// ---------------------------------------------------------------------------
__global__ void k_init() {
    int i = blockIdx.x * blockDim.x + threadIdx.x;   // TOTAL_N threads exactly
    g_deg[i] = 0.f;
    g_t1[i]  = make_float4(0.f, 0.f, 0.f, 0.f);
    if (i < NSTATS) g_stats[i] = 0.0;
}

// ---------------------------------------------------------------------------
// 2) degree: deg[src] += w  (self-loops removed)
// ---------------------------------------------------------------------------
__global__ __launch_bounds__(256) void k_deg(const int* __restrict__ src,
                                             const int* __restrict__ dst,
                                             const float* __restrict__ ew) {
    int i = blockIdx.x * blockDim.x + threadIdx.x;   // NEDGE4 threads
    int4   s = ((const int4*)src)[i];
    int4   d = ((const int4*)dst)[i];
    float4 w = ((const float4*)ew)[i];
    if (s.x != d.x) atomicAdd(&g_deg[s.x], w.x);
    if (s.y != d.y) atomicAdd(&g_deg[s.y], w.y);
    if (s.z != d.z) atomicAdd(&g_deg[s.z], w.z);
    if (s.w != d.w) atomicAdd(&g_deg[s.w], w.w);
}

// ---------------------------------------------------------------------------
// 3) per-node: dis = deg>0 ? rsqrt(max(deg,1e-12)) : 0 ;  T0 = x ;  T2 = -T0
// ---------------------------------------------------------------------------
__global__ void k_node(const float* __restrict__ x) {
    int i = blockIdx.x * blockDim.x + threadIdx.x;   // TOTAL_N threads
    float dg = g_deg[i];
    g_dis[i] = (dg > 0.f) ? rsqrtf(fmaxf(dg, 1e-12f)) : 0.f;
    int b = i >> 15;          // / NPTS
    int n = i & (NPTS - 1);
    const float* xb = x + (size_t)b * 3 * NPTS + n;
    float v0 = xb[0];
    float v1 = xb[NPTS];
    float v2 = xb[2 * NPTS];
    g_t0[i] = make_float4( v0,  v1,  v2, 0.f);
    g_t2[i] = make_float4(-v0, -v1, -v2, 0.f);
}

// ---------------------------------------------------------------------------
// 4) FUSED normw + prop1:
//    nw = (s==d) ? 0 : -dis[s]*ew*dis[d]   (stored for passes 2,3)
//    t1[d] += nw * t0[s]                   (vector RED, zero adds are no-ops)
// ---------------------------------------------------------------------------
__global__ __launch_bounds__(256) void k_prop1(const int* __restrict__ src,
                                               const int* __restrict__ dst,
                                               const float* __restrict__ ew) {
    int i = blockIdx.x * blockDim.x + threadIdx.x;   // NEDGE4 threads
    int4   s = ((const int4*)src)[i];
    int4   d = ((const int4*)dst)[i];
    float4 w = ((const float4*)ew)[i];
    float4 o;
    o.x = (s.x == d.x) ? 0.f : -g_dis[s.x] * w.x * g_dis[d.x];
    o.y = (s.y == d.y) ? 0.f : -g_dis[s.y] * w.y * g_dis[d.y];
    o.z = (s.z == d.z) ? 0.f : -g_dis[s.z] * w.z * g_dis[d.z];
    o.w = (s.w == d.w) ? 0.f : -g_dis[s.w] * w.w * g_dis[d.w];
    ((float4*)g_nw)[i] = o;

    float4 t;
    t = g_t0[s.x]; red_v4(&g_t1[d.x], o.x * t.x, o.x * t.y, o.x * t.z);
    t = g_t0[s.y]; red_v4(&g_t1[d.y], o.y * t.x, o.y * t.y, o.y * t.z);
    t = g_t0[s.z]; red_v4(&g_t1[d.z], o.z * t.x, o.z * t.y, o.z * t.z);
    t = g_t0[s.w]; red_v4(&g_t1[d.w], o.w * t.x, o.w * t.y, o.w * t.z);
}

// ---------------------------------------------------------------------------
// 5) passes 2,3:  tout[d] += 2*nw * tin[s]   (vector RED per edge)
//    PASS 2: t1 -> t2 (t2 pre-init -t0);  PASS 3: t2 -> t3 (t3 pre-init -t1)
// ---------------------------------------------------------------------------
template <int PASS>
__global__ __launch_bounds__(256) void k_prop(const int* __restrict__ src,
                                              const int* __restrict__ dst) {
    int i = blockIdx.x * blockDim.x + threadIdx.x;   // NEDGE4 threads
    int4   s = ((const int4*)src)[i];
    int4   d = ((const int4*)dst)[i];
    float4 w = ((const float4*)g_nw)[i];
    const float4* tin  = (PASS == 2) ? g_t1 : g_t2;
    float4*       tout = (PASS == 2) ? g_t2 : g_t3;
    float4 t;
    float wx = 2.f * w.x, wy = 2.f * w.y, wz = 2.f * w.z, ww = 2.f * w.w;
    t = tin[s.x]; red_v4(&tout[d.x], wx * t.x, wx * t.y, wx * t.z);
    t = tin[s.y]; red_v4(&tout[d.y], wy * t.x, wy * t.y, wy * t.z);
    t = tin[s.z]; red_v4(&tout[d.z], wz * t.x, wz * t.y, wz * t.z);
    t = tin[s.w]; red_v4(&tout[d.w], ww * t.x, ww * t.y, ww * t.z);
}

// T3 initialization = -T1 (after prop1, before prop3 accumulates into it)
__global__ void k_negt1() {
    int i = blockIdx.x * blockDim.x + threadIdx.x;   // TOTAL_N threads
    float4 v = g_t1[i];
    g_t3[i] = make_float4(-v.x, -v.y, -v.z, 0.f);
}

// ---------------------------------------------------------------------------
// 6) stats: Σ v  (12)  and  Σ v vᵀ upper triangle (78), over all nodes.
// ---------------------------------------------------------------------------
__global__ __launch_bounds__(128) void k_stats() {
    int t = blockIdx.x * 128 + threadIdx.x;          // 32768 threads, 8 nodes each
    float acc[NSTATS];
#pragma unroll
    for (int k = 0; k < NSTATS; k++) acc[k] = 0.f;

    for (int it = 0; it < 8; it++) {
        int i = t + it * 32768;
        float v[12];
        float4 a = g_t0[i]; v[0] = a.x; v[1] = a.y; v[2]  = a.z;
        float4 b = g_t1[i]; v[3] = b.x; v[4] = b.y; v[5]  = b.z;
        float4 c = g_t2[i]; v[6] = c.x; v[7] = c.y; v[8]  = c.z;
        float4 d = g_t3[i]; v[9] = d.x; v[10] = d.y; v[11] = d.z;
        int idx = 12;
#pragma unroll
        for (int p = 0; p < 12; p++) {
            acc[p] += v[p];
#pragma unroll
            for (int q = p; q < 12; q++) acc[idx++] += v[p] * v[q];
        }
    }
    int lane = threadIdx.x & 31;
#pragma unroll
    for (int k = 0; k < NSTATS; k++) {
        float x = acc[k];
        x += __shfl_down_sync(0xffffffffu, x, 16);
        x += __shfl_down_sync(0xffffffffu, x, 8);
        x += __shfl_down_sync(0xffffffffu, x, 4);
        x += __shfl_down_sync(0xffffffffu, x, 2);
        x += __shfl_down_sync(0xffffffffu, x, 1);
        if (lane == 0) atomicAdd(&g_stats[k], (double)x);
    }
}

// ---------------------------------------------------------------------------
// 7) BN params: fold exact batch mean/var into per-channel scale/shift.
//    shift = beta − m·scale  (conv bias cancels between value and batch mean)
// ---------------------------------------------------------------------------
__global__ void k_bnparam(const float* __restrict__ weight,  // (12, 128)
                          const float* __restrict__ bias,
                          const float* __restrict__ gamma,
                          const float* __restrict__ beta) {
    __shared__ double S[NSTATS];
    int c = threadIdx.x;                              // 128 threads
    if (c < NSTATS) S[c] = g_stats[c];
    __syncthreads();

    double wv[12];
#pragma unroll
    for (int a = 0; a < 12; a++) wv[a] = (double)weight[a * CBOUT + c];

    const double invN = 1.0 / (double)TOTAL_N;
    double m = 0.0;
#pragma unroll
    for (int a = 0; a < 12; a++) m += S[a] * wv[a];
    m *= invN;

    double q = 0.0;
    int idx = 12;
#pragma unroll
    for (int a = 0; a < 12; a++) {
#pragma unroll
        for (int b = a; b < 12; b++) {
            double term = S[idx++] * wv[a] * wv[b];
            q += (a == b) ? term : 2.0 * term;
        }
    }
    q *= invN;

    double var = q - m * m;
    if (var < 0.0) var = 0.0;
    (void)bias;
    double scale = (double)gamma[c] * rsqrt(var + 1e-5);
    g_sh[c] = (float)((double)beta[c] - m * scale);
#pragma unroll
    for (int a = 0; a < 12; a++)
        g_wfT[c * 12 + a] = (float)(wv[a] * scale);
}

// ---------------------------------------------------------------------------
// 8) final fused GEMV + BN + ReLU, writing directly in (B, C_OUT, N) layout.
// ---------------------------------------------------------------------------
__global__ __launch_bounds__(256) void k_final(float* __restrict__ out) {
    __shared__ __align__(16) float swf[CBOUT * 12];
    __shared__ float ssh[CBOUT];

    int tid = threadIdx.x;
    for (int k = tid; k < CBOUT * 12; k += 256) swf[k] = g_wfT[k];
    if (tid < CBOUT) ssh[tid] = g_sh[tid];
    __syncthreads();

    int w    = tid >> 5;
    int lane = tid & 31;
    int j    = (w & 3) * 32 + lane;        // node within the 128-node tile
    int cg   = w >> 2;                     // channel half: 0 or 1
    int i    = blockIdx.x * 128 + j;

    float4 a = g_t0[i], b = g_t1[i], c = g_t2[i], d = g_t3[i];
    float v[12] = { a.x, a.y, a.z,  b.x, b.y, b.z,
                    c.x, c.y, c.z,  d.x, d.y, d.z };

    int bb = i >> 15;
    int n  = i & (NPTS - 1);
    float* obase = out + ((size_t)bb * CBOUT) * NPTS + n;

#pragma unroll 8
    for (int k = 0; k < 64; k++) {
        int ch = cg * 64 + k;
        const float4* wr = (const float4*)(swf + ch * 12);
        float4 w0 = wr[0], w1 = wr[1], w2 = wr[2];
        float r = ssh[ch];
        r += v[0] * w0.x + v[1]  * w0.y + v[2]  * w0.z + v[3] * w0.w;
        r += v[4] * w1.x + v[5]  * w1.y + v[6]  * w1.z + v[7] * w1.w;
        r += v[8] * w2.x + v[9]  * w2.y + v[10] * w2.z + v[11] * w2.w;
        obase[(size_t)ch * NPTS] = fmaxf(r, 0.f);
    }
}

// ---------------------------------------------------------------------------
// launch
// ---------------------------------------------------------------------------
extern "C" void kernel_launch(void* const* d_in, const int* in_sizes, int n_in,
                              void* d_out, int out_size) {
    const float* x      = (const float*)d_in[0];
    const int*   eidx   = (const int*)d_in[1];
    const float* ew     = (const float*)d_in[2];
    const float* weight = (const float*)d_in[3];
    const float* bias   = (const float*)d_in[4];
    const float* gamma  = (const float*)d_in[5];
    const float* beta   = (const float*)d_in[6];
    float* out = (float*)d_out;

    const int* src = eidx;          // edge_index[0]
    const int* dst = eidx + NEDGE;  // edge_index[1]

    dim3 bN(256);
    dim3 gN(TOTAL_N / 256);         // 1024 blocks, node-sized kernels
    dim3 gE(NEDGE4 / 256);          // 4096 blocks, edge-sized kernels

    k_init  <<<gN, bN>>>();
    k_deg   <<<gE, bN>>>(src, dst, ew);
    k_node  <<<gN, bN>>>(x);
    k_prop1 <<<gE, bN>>>(src, dst, ew);   // nw + t1 = L t0  (fused)
    k_negt1 <<<gN, bN>>>();               // t3  = -t1
    k_prop<2><<<gE, bN>>>(src, dst);      // t2 += 2 L t1   (t2 pre-init -t0)
    k_prop<3><<<gE, bN>>>(src, dst);      // t3 += 2 L t2
    k_stats <<<256, 128>>>();
    k_bnparam<<<1, 128>>>(weight, bias, gamma, beta);
    k_final <<<TOTAL_N / 128, 256>>>(out);
}

// round 5
// speedup vs baseline: 1.5627x; 1.0822x over previous
#include <cuda_runtime.h>
#include <cuda_bf16.h>

// Problem constants
#define TOTAL_N 262144      // B*N nodes
#define NEDGE   4194304
#define NEDGE8  524288      // NEDGE/8
#define NPTS    32768       // N
#define CBOUT   128
#define NSTATS  90          // 12 sums + 78 upper-triangle second moments

// ---------------------------------------------------------------------------
// Device scratch (static allocations only)
// ---------------------------------------------------------------------------
__device__ float  g_deg[TOTAL_N];
__device__ float  g_dis[TOTAL_N];
__device__ float4 g_t0[TOTAL_N];
__device__ float4 g_t1[TOTAL_N];
__device__ float4 g_t2[TOTAL_N];
__device__ float4 g_t3[TOTAL_N];
__device__ float4 g_q[TOTAL_N];     // dis-scaled current Chebyshev vector
__device__ float4 g_acc[TOTAL_N];   // edge-pass accumulator
__device__ double g_stats[NSTATS];
__device__ float  g_wfT[CBOUT * 12];
__device__ float  g_sh[CBOUT];

__device__ __forceinline__ void red_v4(float4* addr, float x, float y, float z) {
    asm volatile("red.global.add.v4.f32 [%0], {%1, %2, %3, %4};"
                 :: "l"(addr), "f"(x), "f"(y), "f"(z), "f"(0.f) : "memory");
}

// ---------------------------------------------------------------------------
// 1) init: zero degree, accumulator, stats
// ---------------------------------------------------------------------------
__global__ void k_init() {
    int i = blockIdx.x * blockDim.x + threadIdx.x;   // TOTAL_N threads
    g_deg[i] = 0.f;
    g_acc[i] = make_float4(0.f, 0.f, 0.f, 0.f);
    if (i < NSTATS) g_stats[i] = 0.0;
}

// ---------------------------------------------------------------------------
// 2) degree: deg[src] += w (self-loops zeroed). 8 edges/thread, batched loads.
// ---------------------------------------------------------------------------
__global__ __launch_bounds__(256) void k_deg(const int* __restrict__ src,
                                             const int* __restrict__ dst,
                                             const float* __restrict__ ew) {
    int i = blockIdx.x * blockDim.x + threadIdx.x;   // NEDGE8 threads
    const int4*   s4 = (const int4*)src;
    const int4*   d4 = (const int4*)dst;
    const float4* w4 = (const float4*)ew;
    int4   sa = s4[2*i], sb = s4[2*i+1];
    int4   da = d4[2*i], db = d4[2*i+1];
    float4 wa = w4[2*i], wb = w4[2*i+1];
    wa.x = (sa.x == da.x) ? 0.f : wa.x;
    wa.y = (sa.y == da.y) ? 0.f : wa.y;
    wa.z = (sa.z == da.z) ? 0.f : wa.z;
    wa.w = (sa.w == da.w) ? 0.f : wa.w;
    wb.x = (sb.x == db.x) ? 0.f : wb.x;
    wb.y = (sb.y == db.y) ? 0.f : wb.y;
    wb.z = (sb.z == db.z) ? 0.f : wb.z;
    wb.w = (sb.w == db.w) ? 0.f : wb.w;
    atomicAdd(&g_deg[sa.x], wa.x);
    atomicAdd(&g_deg[sa.y], wa.y);
    atomicAdd(&g_deg[sa.z], wa.z);
    atomicAdd(&g_deg[sa.w], wa.w);
    atomicAdd(&g_deg[sb.x], wb.x);
    atomicAdd(&g_deg[sb.y], wb.y);
    atomicAdd(&g_deg[sb.z], wb.z);
    atomicAdd(&g_deg[sb.w], wb.w);
}

// ---------------------------------------------------------------------------
// 3) node pass 0: dis, T0 = x, q = dis*T0
// ---------------------------------------------------------------------------
__global__ void k_node0(const float* __restrict__ x) {
    int i = blockIdx.x * blockDim.x + threadIdx.x;   // TOTAL_N threads
    float dg  = g_deg[i];
    float dis = (dg > 0.f) ? rsqrtf(fmaxf(dg, 1e-12f)) : 0.f;
    g_dis[i] = dis;
    int b = i >> 15;
    int n = i & (NPTS - 1);
    const float* xb = x + (size_t)b * 3 * NPTS + n;
    float v0 = xb[0];
    float v1 = xb[NPTS];
    float v2 = xb[2 * NPTS];
    g_t0[i] = make_float4(v0, v1, v2, 0.f);
    g_q[i]  = make_float4(dis * v0, dis * v1, dis * v2, 0.f);
}

// ---------------------------------------------------------------------------
// 4) edge pass (shared by all 3 props): acc[dst] += w * q[src]
//    8 edges/thread; gathers front-batched for MLP; RED has no return dep.
// ---------------------------------------------------------------------------
__global__ __launch_bounds__(256) void k_edge(const int* __restrict__ src,
                                              const int* __restrict__ dst,
                                              const float* __restrict__ ew) {
    int i = blockIdx.x * blockDim.x + threadIdx.x;   // NEDGE8 threads
    const int4*   s4 = (const int4*)src;
    const int4*   d4 = (const int4*)dst;
    const float4* w4 = (const float4*)ew;
    int4   sa = s4[2*i], sb = s4[2*i+1];
    int4   da = d4[2*i], db = d4[2*i+1];
    float4 wa = w4[2*i], wb = w4[2*i+1];
    wa.x = (sa.x == da.x) ? 0.f : wa.x;
    wa.y = (sa.y == da.y) ? 0.f : wa.y;
    wa.z = (sa.z == da.z) ? 0.f : wa.z;
    wa.w = (sa.w == da.w) ? 0.f : wa.w;
    wb.x = (sb.x == db.x) ? 0.f : wb.x;
    wb.y = (sb.y == db.y) ? 0.f : wb.y;
    wb.z = (sb.z == db.z) ? 0.f : wb.z;
    wb.w = (sb.w == db.w) ? 0.f : wb.w;

    // batch all 8 random gathers
    float4 t0 = g_q[sa.x];
    float4 t1 = g_q[sa.y];
    float4 t2 = g_q[sa.z];
    float4 t3 = g_q[sa.w];
    float4 t4 = g_q[sb.x];
    float4 t5 = g_q[sb.y];
    float4 t6 = g_q[sb.z];
    float4 t7 = g_q[sb.w];

    red_v4(&g_acc[da.x], wa.x * t0.x, wa.x * t0.y, wa.x * t0.z);
    red_v4(&g_acc[da.y], wa.y * t1.x, wa.y * t1.y, wa.y * t1.z);
    red_v4(&g_acc[da.z], wa.z * t2.x, wa.z * t2.y, wa.z * t2.z);
    red_v4(&g_acc[da.w], wa.w * t3.x, wa.w * t3.y, wa.w * t3.z);
    red_v4(&g_acc[db.x], wb.x * t4.x, wb.x * t4.y, wb.x * t4.z);
    red_v4(&g_acc[db.y], wb.y * t5.x, wb.y * t5.y, wb.y * t5.z);
    red_v4(&g_acc[db.z], wb.z * t6.x, wb.z * t6.y, wb.z * t6.z);
    red_v4(&g_acc[db.w], wb.w * t7.x, wb.w * t7.y, wb.w * t7.z);
}

// ---------------------------------------------------------------------------
// 5) node pass 1: T1 = -dis*acc ; q = dis*T1 ; acc = 0
// ---------------------------------------------------------------------------
__global__ void k_node1() {
    int i = blockIdx.x * blockDim.x + threadIdx.x;
    float4 a  = g_acc[i];
    float dis = g_dis[i];
    float x = -dis * a.x, y = -dis * a.y, z = -dis * a.z;
    g_t1[i]  = make_float4(x, y, z, 0.f);
    g_q[i]   = make_float4(dis * x, dis * y, dis * z, 0.f);
    g_acc[i] = make_float4(0.f, 0.f, 0.f, 0.f);
}

// ---------------------------------------------------------------------------
// 6) node pass 2: T2 = -2*dis*acc - T0 ; q = dis*T2 ; acc = 0
// ---------------------------------------------------------------------------
__global__ void k_node2() {
    int i = blockIdx.x * blockDim.x + threadIdx.x;
    float4 a  = g_acc[i];
    float dis = g_dis[i];
    float4 t0 = g_t0[i];
    float x = -2.f * dis * a.x - t0.x;
    float y = -2.f * dis * a.y - t0.y;
    float z = -2.f * dis * a.z - t0.z;
    g_t2[i]  = make_float4(x, y, z, 0.f);
    g_q[i]   = make_float4(dis * x, dis * y, dis * z, 0.f);
    g_acc[i] = make_float4(0.f, 0.f, 0.f, 0.f);
}

// ---------------------------------------------------------------------------
// 7) node pass 3 + stats fused: T3 = -2*dis*acc - T1, then accumulate
//    Σv (12) and Σvvᵀ upper triangle (78). 8 nodes/thread to amortize atomics.
// ---------------------------------------------------------------------------
__global__ __launch_bounds__(128) void k_node3_stats() {
    int t = blockIdx.x * 128 + threadIdx.x;          // 32768 threads
    float acc[NSTATS];
#pragma unroll
    for (int k = 0; k < NSTATS; k++) acc[k] = 0.f;

    for (int it = 0; it < 8; it++) {
        int i = t + it * 32768;
        float4 a  = g_acc[i];
        float dis = g_dis[i];
        float4 b  = g_t1[i];
        float tx = -2.f * dis * a.x - b.x;
        float ty = -2.f * dis * a.y - b.y;
        float tz = -2.f * dis * a.z - b.z;
        g_t3[i] = make_float4(tx, ty, tz, 0.f);

        float v[12];
        float4 p = g_t0[i]; v[0] = p.x; v[1] = p.y; v[2]  = p.z;
        v[3] = b.x; v[4] = b.y; v[5] = b.z;
        float4 c = g_t2[i]; v[6] = c.x; v[7] = c.y; v[8]  = c.z;
        v[9] = tx; v[10] = ty; v[11] = tz;
        int idx = 12;
#pragma unroll
        for (int p2 = 0; p2 < 12; p2++) {
            acc[p2] += v[p2];
#pragma unroll
            for (int q = p2; q < 12; q++) acc[idx++] += v[p2] * v[q];
        }
    }
    int lane = threadIdx.x & 31;
#pragma unroll
    for (int k = 0; k < NSTATS; k++) {
        float x = acc[k];
        x += __shfl_down_sync(0xffffffffu, x, 16);
        x += __shfl_down_sync(0xffffffffu, x, 8);
        x += __shfl_down_sync(0xffffffffu, x, 4);
        x += __shfl_down_sync(0xffffffffu, x, 2);
        x += __shfl_down_sync(0xffffffffu, x, 1);
        if (lane == 0) atomicAdd(&g_stats[k], (double)x);
    }
}

// ---------------------------------------------------------------------------
// 8) BN params: fold exact batch mean/var into scale/shift.
//    shift = beta − m·scale (conv bias cancels against batch mean)
// ---------------------------------------------------------------------------
__global__ void k_bnparam(const float* __restrict__ weight,  // (12, 128)
                          const float* __restrict__ bias,
                          const float* __restrict__ gamma,
                          const float* __restrict__ beta) {
    __shared__ double S[NSTATS];
    int c = threadIdx.x;                              // 128 threads
    if (c < NSTATS) S[c] = g_stats[c];
    __syncthreads();

    double wv[12];
#pragma unroll
    for (int a = 0; a < 12; a++) wv[a] = (double)weight[a * CBOUT + c];

    const double invN = 1.0 / (double)TOTAL_N;
    double m = 0.0;
#pragma unroll
    for (int a = 0; a < 12; a++) m += S[a] * wv[a];
    m *= invN;

    double q = 0.0;
    int idx = 12;
#pragma unroll
    for (int a = 0; a < 12; a++) {
#pragma unroll
        for (int b = a; b < 12; b++) {
            double term = S[idx++] * wv[a] * wv[b];
            q += (a == b) ? term : 2.0 * term;
        }
    }
    q *= invN;

    double var = q - m * m;
    if (var < 0.0) var = 0.0;
    (void)bias;
    double scale = (double)gamma[c] * rsqrt(var + 1e-5);
    g_sh[c] = (float)((double)beta[c] - m * scale);
#pragma unroll
    for (int a = 0; a < 12; a++)
        g_wfT[c * 12 + a] = (float)(wv[a] * scale);
}

// ---------------------------------------------------------------------------
// 9) final fused GEMV + BN + ReLU, writing directly in (B, C_OUT, N) layout.
// ---------------------------------------------------------------------------
__global__ __launch_bounds__(256) void k_final(float* __restrict__ out) {
    __shared__ __align__(16) float swf[CBOUT * 12];
    __shared__ float ssh[CBOUT];

    int tid = threadIdx.x;
    for (int k = tid; k < CBOUT * 12; k += 256) swf[k] = g_wfT[k];
    if (tid < CBOUT) ssh[tid] = g_sh[tid];
    __syncthreads();

    int w    = tid >> 5;
    int lane = tid & 31;
    int j    = (w & 3) * 32 + lane;
    int cg   = w >> 2;
    int i    = blockIdx.x * 128 + j;

    float4 a = g_t0[i], b = g_t1[i], c = g_t2[i], d = g_t3[i];
    float v[12] = { a.x, a.y, a.z,  b.x, b.y, b.z,
                    c.x, c.y, c.z,  d.x, d.y, d.z };

    int bb = i >> 15;
    int n  = i & (NPTS - 1);
    float* obase = out + ((size_t)bb * CBOUT) * NPTS + n;

#pragma unroll 8
    for (int k = 0; k < 64; k++) {
        int ch = cg * 64 + k;
        const float4* wr = (const float4*)(swf + ch * 12);
        float4 w0 = wr[0], w1 = wr[1], w2 = wr[2];
        float r = ssh[ch];
        r += v[0] * w0.x + v[1]  * w0.y + v[2]  * w0.z + v[3] * w0.w;
        r += v[4] * w1.x + v[5]  * w1.y + v[6]  * w1.z + v[7] * w1.w;
        r += v[8] * w2.x + v[9]  * w2.y + v[10] * w2.z + v[11] * w2.w;
        obase[(size_t)ch * NPTS] = fmaxf(r, 0.f);
    }
}

// ---------------------------------------------------------------------------
// launch
// ---------------------------------------------------------------------------
extern "C" void kernel_launch(void* const* d_in, const int* in_sizes, int n_in,
                              void* d_out, int out_size) {
    const float* x      = (const float*)d_in[0];
    const int*   eidx   = (const int*)d_in[1];
    const float* ew     = (const float*)d_in[2];
    const float* weight = (const float*)d_in[3];
    const float* bias   = (const float*)d_in[4];
    const float* gamma  = (const float*)d_in[5];
    const float* beta   = (const float*)d_in[6];
    float* out = (float*)d_out;

    const int* src = eidx;          // edge_index[0]
    const int* dst = eidx + NEDGE;  // edge_index[1]

    dim3 bN(256);
    dim3 gN(TOTAL_N / 256);         // 1024 blocks (node kernels)
    dim3 gE(NEDGE8 / 256);          // 2048 blocks (edge kernels, 8 edges/thread)

    k_init  <<<gN, bN>>>();
    k_deg   <<<gE, bN>>>(src, dst, ew);
    k_node0 <<<gN, bN>>>(x);
    k_edge  <<<gE, bN>>>(src, dst, ew);   // acc = A_w q0
    k_node1 <<<gN, bN>>>();               // T1, q1
    k_edge  <<<gE, bN>>>(src, dst, ew);   // acc = A_w q1
    k_node2 <<<gN, bN>>>();               // T2, q2
    k_edge  <<<gE, bN>>>(src, dst, ew);   // acc = A_w q2
    k_node3_stats <<<256, 128>>>();       // T3 + BN stats
    k_bnparam<<<1, 128>>>(weight, bias, gamma, beta);
    k_final <<<TOTAL_N / 128, 256>>>(out);
}